// round 9
// baseline (speedup 1.0000x reference)
#include <cuda_runtime.h>

#define B 16
#define A 3
#define C 80
#define H 76
#define W 76
#define T 50
#define HW (H*W)                  // 5776
#define CNT (B*A*H*W)             // 277248
#define CNT4 (CNT/4)              // 69312 float4 elems across 48 conf planes
#define Q4 (HW/4)                 // 1444 float4 per plane
#define CH 85
#define NTHREADS 256
#define NWARPS (NTHREADS/32)      // 8
#define P 7                        // replicas per batch: 56 warps >= T
#define NB_CONF 36                 // conf blocks
#define CREADS 8                   // float4 reads per conf thread
#define CSTRIDE (NB_CONF * NTHREADS)   // 9216
#define NB_TGT (B * P)                  // 112
#define NB_TOTAL (NB_CONF + NB_TGT)     // 148 = one wave
#define BMW ((A*HW + 31) / 32)          // 542 bitmap words

// Persistent state (self-resetting): 10 accumulators + completion counter.
// 0 sx, 1 sy, 2 sw, 3 sh, 4 sconf_obj, 5 scls, 6 n_m,
// 7 dense_conf_sum, 8 sub_conf_sum (hit cells), 9 n_hit
__device__ float        g_acc[10];
__device__ unsigned int g_done;

// min(softplus(z), 100) == -clip(log(1-sigmoid(z)), -100)
__device__ __forceinline__ float sp_pos(float z) {
    float sp = fmaxf(z, 0.f) + __logf(1.f + __expf(-fabsf(z)));
    return fminf(sp, 100.f);
}
// bce(sigmoid(z), t) with reference clip semantics
__device__ __forceinline__ float bce_z(float z, float t) {
    return t * sp_pos(-z) + (1.f - t) * sp_pos(z);
}

__global__ void __launch_bounds__(NTHREADS)
yolo_loss_all(const float* __restrict__ inp, const float* __restrict__ tgt,
              float* __restrict__ out) {
    const int tid = threadIdx.x;
    const int bid = blockIdx.x;
    const int wid = tid >> 5, lid = tid & 31;

    __shared__ float red[10][NWARPS];
    __shared__ unsigned int s_last;

    float vals[10];
    #pragma unroll
    for (int j = 0; j < 10; j++) vals[j] = 0.f;

    if (bid < NB_CONF) {
        // ======== dense conf pass: 8 float4 per thread (MLP=8) ========
        int v = bid * NTHREADS + tid;
        float4 q[CREADS];
        bool   live[CREADS];
        #pragma unroll
        for (int r = 0; r < CREADS; r++) {
            int e = v + r * CSTRIDE;
            live[r] = (e < CNT4);
            if (live[r]) {
                int plane = e / Q4;            // 0..47
                int j = e - plane * Q4;
                q[r] = ((const float4*)(inp + (size_t)(CH * plane + 4) * HW))[j];
            }
        }
        float acc = 0.f;
        #pragma unroll
        for (int r = 0; r < CREADS; r++)
            if (live[r])
                acc += sp_pos(q[r].x) + sp_pos(q[r].y) + sp_pos(q[r].z) + sp_pos(q[r].w);
        // single-slot block reduction
        #pragma unroll
        for (int o = 16; o > 0; o >>= 1) acc += __shfl_down_sync(0xffffffffu, acc, o);
        if (lid == 0) red[0][wid] = acc;
        __syncthreads();
        if (wid == 0) {
            float vv = (lid < NWARPS) ? red[0][lid] : 0.f;
            #pragma unroll
            for (int o = 4; o > 0; o >>= 1) vv += __shfl_down_sync(0xffffffffu, vv, o);
            if (lid == 0) atomicAdd(&g_acc[7], vv);
        }
    } else {
        // ======== target blocks: P=7 replicas per batch, 1 target per warp ====
        const int tb  = bid - NB_CONF;
        const int b   = tb / P;
        const int sub = tb - b * P;

        __shared__ unsigned int bm[BMW];            // used by sub==0 only
        __shared__ int   s_cell[T];
        __shared__ int   s_cls[T];
        __shared__ float s_tx[T], s_ty[T], s_tw[T], s_th[T];
        __shared__ unsigned char s_flag[T];
        __shared__ unsigned int w_c0[T], w_c1[T], w_c2[T];

        const float aw[3] = {1.25f, 2.0f, 4.125f};   // ANCHORS / (608/76)
        const float ah[3] = {1.625f, 3.75f, 2.875f};

        if (sub == 0)
            for (int i = tid; i < BMW; i += NTHREADS) bm[i] = 0u;
        if (tid < T) s_flag[tid] = 0;
        __syncthreads();

        // ---- phase A: geometry (all replicas); dedup/subtract (sub 0 only) ----
        if (tid < T) {
            const float* tp = tgt + (size_t)(b * T + tid) * 5;
            float c0 = tp[0], c1 = tp[1], c2 = tp[2], c3 = tp[3], c4 = tp[4];
            bool valid = (c0 + c1 + c2 + c3 + c4) != 0.f;
            float gx = c1 * (float)W, gy = c2 * (float)H;
            float gw = c3 * (float)W, gh = c4 * (float)H;
            int gi = (int)gx, gj = (int)gy;
            bool inb = (gj >= 0) && (gj < H) && (gi >= 0) && (gi < W);
            bool ok = valid && (gj < H) && (gi < W);

            // conf preloads (sub 0 only), issued before iou/atomics
            float zc[3];
            zc[0] = zc[1] = zc[2] = 0.f;
            if (sub == 0 && valid && inb) {
                #pragma unroll
                for (int a = 0; a < A; a++)
                    zc[a] = inp[(size_t)(CH * (3 * b + a) + 4) * HW + gj * W + gi];
            }

            float a1 = (gw + 1.f) * (gh + 1.f);
            float bestv = -1.f; int best = 0;
            #pragma unroll
            for (int a = 0; a < A; a++) {
                float inter = fmaxf(fminf(gw, aw[a]) + 1.f, 0.f) *
                              fmaxf(fminf(gh, ah[a]) + 1.f, 0.f);
                float a2 = (aw[a] + 1.f) * (ah[a] + 1.f);
                float iou = inter / (a1 + a2 - inter + 1e-16f);
                if (iou > bestv) { bestv = iou; best = a; }
                if (sub == 0 && valid && iou > 0.5f && inb) {
                    int li = (a * H + gj) * W + gi;            // index within batch
                    unsigned old = atomicOr(&bm[li >> 5], 1u << (li & 31));
                    if (!(old & (1u << (li & 31)))) {
                        vals[8] += sp_pos(zc[a]);   // subtracted from dense sum later
                        vals[9] += 1.f;
                    }
                }
            }
            s_cell[tid] = ok ? ((b * A + best) * H + gj) * W + gi : -1;
            s_cls[tid]  = (int)c0;
            s_tx[tid]   = gx - (float)gi;
            s_ty[tid]   = gy - (float)gj;
            s_tw[tid]   = __logf(gw / aw[best] + 1e-16f);
            s_th[tid]   = __logf(gh / ah[best] + 1e-16f);
        }
        __syncthreads();

        // ---- phase B: PREFETCH gather loads, one target per warp.
        //      Depends only on s_cell -> overlaps with winner resolution. ----
        const int t = sub * NWARPS + wid;           // this warp's target, 0..55
        float z0 = 0.f, z1 = 0.f, z2 = 0.f;
        const bool cand = (t < T) && (s_cell[t] >= 0);
        if (cand) {
            int cell  = s_cell[t];
            int plane = cell / HW;               // b*A + anchor
            int rem   = cell - plane * HW;
            const float* p = inp + (size_t)CH * plane * HW + rem;
            z0 = p[(size_t)lid * HW];
            z1 = p[(size_t)(lid + 32) * HW];
            z2 = (lid < CH - 64) ? p[(size_t)(lid + 64) * HW] : 0.f;
        }

        // ---- phase C: winner flags (last-target-wins, no break -> pipelined)
        //      + per-target multi-hot class masks for winners ----
        if (tid < T) {
            int cell = s_cell[tid];
            if (cell >= 0) {
                bool win = true;
                #pragma unroll 10
                for (int u = tid + 1; u < T; u++)
                    win &= (s_cell[u] != cell);
                if (win) {
                    unsigned cm0 = 0, cm1 = 0, cm2 = 0;
                    #pragma unroll 10
                    for (int u = 0; u < T; u++) {
                        if (s_cell[u] == cell) {
                            int cc = s_cls[u];
                            if (cc < 32)      cm0 |= 1u << cc;
                            else if (cc < 64) cm1 |= 1u << (cc - 32);
                            else              cm2 |= 1u << (cc - 64);
                        }
                    }
                    w_c0[tid] = cm0; w_c1[tid] = cm1; w_c2[tid] = cm2;
                    s_flag[tid] = 1;
                }
            }
        }
        __syncthreads();

        // ---- phase D: compute on prefetched data, winners only ----
        float a0 = 0.f, a1 = 0.f, a2 = 0.f, a3 = 0.f, a4 = 0.f, a5 = 0.f;
        if (cand && s_flag[t]) {
            float tx = s_tx[t], ty = s_ty[t], tw = s_tw[t], th = s_th[t];
            unsigned cm0 = w_c0[t], cm1 = w_c1[t], cm2 = w_c2[t];
            // round 1: channels 0..31 (specials live here)
            if (lid == 0)      a0 = bce_z(z0, tx);
            else if (lid == 1) a1 = bce_z(z0, ty);
            else if (lid == 2) { float d = z0 - tw; a2 = d * d; }
            else if (lid == 3) { float d = z0 - th; a3 = d * d; }
            else if (lid == 4) a4 = sp_pos(-z0);           // bce(conf, 1)
            else {
                int c = lid - 5;                            // 0..26
                a5 += (cm0 >> c) & 1u ? sp_pos(-z0) : sp_pos(z0);
            }
            // round 2: channels 32..63 -> classes 27..58
            {
                int c = lid + 27;
                unsigned bit = (c < 32) ? (cm0 >> c) : (cm1 >> (c - 32));
                a5 += bit & 1u ? sp_pos(-z1) : sp_pos(z1);
            }
            // round 3: channels 64..84 -> classes 59..79 (lanes 0..20)
            if (lid < CH - 64) {
                int c = lid + 59;
                unsigned bit = (c < 64) ? (cm1 >> (c - 32)) : (cm2 >> (c - 64));
                a5 += bit & 1u ? sp_pos(-z2) : sp_pos(z2);
            }
        }
        vals[0] = a0; vals[1] = a1; vals[2] = a2;
        vals[3] = a3; vals[4] = a4; vals[5] = a5;
        // n_m: block-wide winner count, contributed ONCE (sub 0, thread 0).
        if (sub == 0 && tid == 0) {
            int n = 0;
            #pragma unroll 10
            for (int u = 0; u < T; u++) n += s_flag[u];
            vals[6] = (float)n;
        }

        // ---- 10-slot block reduction, one atomic per live slot ----
        #pragma unroll
        for (int j = 0; j < 10; j++) {
            float vv = vals[j];
            #pragma unroll
            for (int o = 16; o > 0; o >>= 1) vv += __shfl_down_sync(0xffffffffu, vv, o);
            if (lid == 0) red[j][wid] = vv;
        }
        __syncthreads();
        if (wid == 0) {
            #pragma unroll
            for (int j = 0; j < 10; j++) {
                float vv = (lid < NWARPS) ? red[j][lid] : 0.f;
                #pragma unroll
                for (int o = 4; o > 0; o >>= 1) vv += __shfl_down_sync(0xffffffffu, vv, o);
                if (lid == 0 && vv != 0.f) atomicAdd(&g_acc[j], vv);
            }
        }
    }

    // ======== completion: last block finalizes + resets state ========
    __threadfence();
    __syncthreads();
    if (tid == 0) s_last = atomicAdd(&g_done, 1u);
    __syncthreads();
    if (s_last == (unsigned)(NB_TOTAL - 1)) {
        if (tid == 0) {
            volatile float* g = g_acc;
            const float inv = 1.f / (float)CNT;
            float nm  = g[6];
            float nnm = (float)CNT - g[9];
            float lx = (g[0] * inv) / nm;
            float ly = (g[1] * inv) / nm;
            float lw = (g[2] * inv) / nm;
            float lh = (g[3] * inv) / nm;
            float lc = (g[4] * inv) / nm + 0.5f * ((g[7] - g[8]) * inv) / nnm;
            float lcls = g[5] / (nm * (float)C) / nm;
            float loss = 2.5f * (lx + ly) + 2.5f * (lw + lh) + lc + lcls;
            out[0] = loss; out[1] = lx; out[2] = ly; out[3] = lw;
            out[4] = lh;   out[5] = lc; out[6] = lcls;
        }
        __syncthreads();          // out written before reset
        if (tid < 10) g_acc[tid] = 0.f;
        __syncthreads();
        if (tid == 0) g_done = 0u;
    }
}

extern "C" void kernel_launch(void* const* d_in, const int* in_sizes, int n_in,
                              void* d_out, int out_size) {
    const float* inp = (const float*)d_in[0];
    const float* tgt = (const float*)d_in[1];
    if (n_in >= 2 && in_sizes[0] == B * T * 5) {   // defensive order check
        inp = (const float*)d_in[1];
        tgt = (const float*)d_in[0];
    }
    yolo_loss_all<<<NB_TOTAL, NTHREADS>>>(inp, tgt, (float*)d_out);
}

// round 10
// speedup vs baseline: 1.3692x; 1.3692x over previous
#include <cuda_runtime.h>

#define B 16
#define A 3
#define C 80
#define H 76
#define W 76
#define T 50
#define HW (H*W)                  // 5776
#define CNT (B*A*H*W)             // 277248
#define CNT4 (CNT/4)              // 69312 float4 elems across 48 conf planes
#define Q4 (HW/4)                 // 1444 float4 per plane
#define CH 85
#define NTHREADS 256
#define NWARPS (NTHREADS/32)      // 8
#define P 7                        // replicas per batch: 56 warps >= T
#define NB_CONF 36                 // conf blocks
#define CREADS 8                   // float4 reads per conf thread
#define CSTRIDE (NB_CONF * NTHREADS)   // 9216
#define NB_TGT (B * P)                  // 112
#define NB_TOTAL (NB_CONF + NB_TGT)     // 148 = one wave
#define BMW ((A*HW + 31) / 32)          // 542 bitmap words

// Persistent state (self-resetting): 10 accumulators + completion counter.
// 0 sx, 1 sy, 2 sw, 3 sh, 4 sconf_obj, 5 scls, 6 n_m,
// 7 dense_conf_sum, 8 sub_conf_sum (hit cells), 9 n_hit
__device__ float        g_acc[10];
__device__ unsigned int g_done;

// min(softplus(z), 100) == -clip(log(1-sigmoid(z)), -100)
__device__ __forceinline__ float sp_pos(float z) {
    float sp = fmaxf(z, 0.f) + __logf(1.f + __expf(-fabsf(z)));
    return fminf(sp, 100.f);
}
// bce(sigmoid(z), t) with reference clip semantics
__device__ __forceinline__ float bce_z(float z, float t) {
    return t * sp_pos(-z) + (1.f - t) * sp_pos(z);
}

__global__ void __launch_bounds__(NTHREADS)
yolo_loss_all(const float* __restrict__ inp, const float* __restrict__ tgt,
              float* __restrict__ out) {
    const int tid = threadIdx.x;
    const int bid = blockIdx.x;
    const int wid = tid >> 5, lid = tid & 31;

    __shared__ float red[10][NWARPS];
    __shared__ unsigned int s_last;

    float vals[10];
    #pragma unroll
    for (int j = 0; j < 10; j++) vals[j] = 0.f;

    if (bid < NB_CONF) {
        // ======== dense conf pass: 8 float4 per thread (MLP=8) ========
        int v = bid * NTHREADS + tid;
        float4 q[CREADS];
        bool   live[CREADS];
        #pragma unroll
        for (int r = 0; r < CREADS; r++) {
            int e = v + r * CSTRIDE;
            live[r] = (e < CNT4);
            if (live[r]) {
                int plane = e / Q4;            // 0..47
                int j = e - plane * Q4;
                q[r] = ((const float4*)(inp + (size_t)(CH * plane + 4) * HW))[j];
            }
        }
        float acc = 0.f;
        #pragma unroll
        for (int r = 0; r < CREADS; r++)
            if (live[r])
                acc += sp_pos(q[r].x) + sp_pos(q[r].y) + sp_pos(q[r].z) + sp_pos(q[r].w);
        // single-slot block reduction
        #pragma unroll
        for (int o = 16; o > 0; o >>= 1) acc += __shfl_down_sync(0xffffffffu, acc, o);
        if (lid == 0) red[0][wid] = acc;
        __syncthreads();
        if (wid == 0) {
            float vv = (lid < NWARPS) ? red[0][lid] : 0.f;
            #pragma unroll
            for (int o = 4; o > 0; o >>= 1) vv += __shfl_down_sync(0xffffffffu, vv, o);
            if (lid == 0) atomicAdd(&g_acc[7], vv);
        }
    } else {
        // ======== target blocks: P=7 replicas per batch, 1 target per warp.
        // Each warp redundantly computes ITS OWN target's geometry directly
        // from tgt, so the 85-channel gather issues before the phase-A
        // barrier; winner resolution is warp-local ballots (no extra sync).
        const int tb  = bid - NB_CONF;
        const int b   = tb / P;
        const int sub = tb - b * P;

        __shared__ unsigned int bm[BMW];            // used by sub==0 only
        __shared__ int s_cell[T];
        __shared__ int s_cls[T];

        const float aw[3] = {1.25f, 2.0f, 4.125f};   // ANCHORS / (608/76)
        const float ah[3] = {1.625f, 3.75f, 2.875f};

        // ---- hoisted loads: warp-own target row + per-thread target row ----
        const int t = sub * NWARPS + wid;           // this warp's target, 0..55
        const bool tmine = (t < T);
        float m0 = 0.f, m1 = 0.f, m2 = 0.f, m3 = 0.f, m4 = 0.f;
        if (tmine) {
            const float* tp = tgt + (size_t)(b * T + t) * 5;
            m0 = tp[0]; m1 = tp[1]; m2 = tp[2]; m3 = tp[3]; m4 = tp[4];
        }
        float c0 = 0.f, c1 = 0.f, c2 = 0.f, c3 = 0.f, c4 = 0.f;
        if (tid < T) {
            const float* tp = tgt + (size_t)(b * T + tid) * 5;
            c0 = tp[0]; c1 = tp[1]; c2 = tp[2]; c3 = tp[3]; c4 = tp[4];
        }
        if (sub == 0)
            for (int i = tid; i < BMW; i += NTHREADS) bm[i] = 0u;
        __syncthreads();                            // bm ready before atomicOr

        // ---- warp-local geometry for own target; gather issues here ----
        float z0 = 0.f, z1 = 0.f, z2 = 0.f;
        float wtx = 0.f, wty = 0.f, wtw = 0.f, wth = 0.f;
        int   wcell = -1;
        bool  cand = false;
        if (tmine) {
            bool valid = (m0 + m1 + m2 + m3 + m4) != 0.f;
            float gx = m1 * (float)W, gy = m2 * (float)H;
            float gw = m3 * (float)W, gh = m4 * (float)H;
            int gi = (int)gx, gj = (int)gy;
            bool ok = valid && (gj < H) && (gi < W);
            if (ok) {
                float a1 = (gw + 1.f) * (gh + 1.f);
                float bestv = -1.f; int best = 0;
                #pragma unroll
                for (int a = 0; a < A; a++) {
                    float inter = fmaxf(fminf(gw, aw[a]) + 1.f, 0.f) *
                                  fmaxf(fminf(gh, ah[a]) + 1.f, 0.f);
                    float a2 = (aw[a] + 1.f) * (ah[a] + 1.f);
                    float iou = inter / (a1 + a2 - inter + 1e-16f);
                    if (iou > bestv) { bestv = iou; best = a; }
                }
                wcell = ((b * A + best) * H + gj) * W + gi;
                wtx = gx - (float)gi;
                wty = gy - (float)gj;
                wtw = __logf(gw / aw[best] + 1e-16f);
                wth = __logf(gh / ah[best] + 1e-16f);
                cand = true;
                int plane = wcell / HW;
                int rem   = wcell - plane * HW;
                const float* p = inp + (size_t)CH * plane * HW + rem;
                z0 = p[(size_t)lid * HW];
                z1 = p[(size_t)(lid + 32) * HW];
                z2 = (lid < CH - 64) ? p[(size_t)(lid + 64) * HW] : 0.f;
            }
        }

        // ---- phase A (thread-level): fill s_cell/s_cls; sub-0 dedup ----
        if (tid < T) {
            bool valid = (c0 + c1 + c2 + c3 + c4) != 0.f;
            float gx = c1 * (float)W, gy = c2 * (float)H;
            float gw = c3 * (float)W, gh = c4 * (float)H;
            int gi = (int)gx, gj = (int)gy;
            bool inb = (gj >= 0) && (gj < H) && (gi >= 0) && (gi < W);
            bool ok = valid && (gj < H) && (gi < W);

            float zc[3];
            zc[0] = zc[1] = zc[2] = 0.f;
            if (sub == 0 && valid && inb) {
                #pragma unroll
                for (int a = 0; a < A; a++)
                    zc[a] = inp[(size_t)(CH * (3 * b + a) + 4) * HW + gj * W + gi];
            }

            float a1 = (gw + 1.f) * (gh + 1.f);
            float bestv = -1.f; int best = 0;
            #pragma unroll
            for (int a = 0; a < A; a++) {
                float inter = fmaxf(fminf(gw, aw[a]) + 1.f, 0.f) *
                              fmaxf(fminf(gh, ah[a]) + 1.f, 0.f);
                float a2 = (aw[a] + 1.f) * (ah[a] + 1.f);
                float iou = inter / (a1 + a2 - inter + 1e-16f);
                if (iou > bestv) { bestv = iou; best = a; }
                if (sub == 0 && valid && iou > 0.5f && inb) {
                    int li = (a * H + gj) * W + gi;            // index within batch
                    unsigned old = atomicOr(&bm[li >> 5], 1u << (li & 31));
                    if (!(old & (1u << (li & 31)))) {
                        vals[8] += sp_pos(zc[a]);   // subtracted from dense sum later
                        vals[9] += 1.f;
                    }
                }
            }
            s_cell[tid] = ok ? ((b * A + best) * H + gj) * W + gi : -1;
            s_cls[tid]  = (int)c0;
        }
        __syncthreads();                            // s_cell/s_cls complete

        // ---- warp-local winner resolution + multi-hot masks + compute ----
        float a0 = 0.f, a1 = 0.f, a2 = 0.f, a3 = 0.f, a4 = 0.f, a5 = 0.f;
        if (cand) {                                 // warp-uniform
            const int u2 = lid + 32;
            int cu1 = s_cell[lid];
            int cu2 = (u2 < T) ? s_cell[u2] : -2;
            bool mt1 = (cu1 == wcell);
            bool mt2 = (cu2 == wcell);
            // last-target-wins: any matching target with larger index?
            unsigned later = __ballot_sync(0xffffffffu,
                                           (mt1 && lid > t) || (mt2 && u2 > t));
            if (later == 0) {                       // this warp's target wins
                unsigned cm0 = 0, cm1 = 0, cm2 = 0;
                if (mt1) {
                    int cc = s_cls[lid];
                    if (cc < 32)      cm0 |= 1u << cc;
                    else if (cc < 64) cm1 |= 1u << (cc - 32);
                    else              cm2 |= 1u << (cc - 64);
                }
                if (mt2) {
                    int cc = s_cls[u2];
                    if (cc < 32)      cm0 |= 1u << cc;
                    else if (cc < 64) cm1 |= 1u << (cc - 32);
                    else              cm2 |= 1u << (cc - 64);
                }
                cm0 = __reduce_or_sync(0xffffffffu, cm0);
                cm1 = __reduce_or_sync(0xffffffffu, cm1);
                cm2 = __reduce_or_sync(0xffffffffu, cm2);

                // round 1: channels 0..31 (specials live here)
                if (lid == 0)      a0 = bce_z(z0, wtx);
                else if (lid == 1) a1 = bce_z(z0, wty);
                else if (lid == 2) { float d = z0 - wtw; a2 = d * d; }
                else if (lid == 3) { float d = z0 - wth; a3 = d * d; }
                else if (lid == 4) a4 = sp_pos(-z0);       // bce(conf, 1)
                else {
                    int c = lid - 5;                        // 0..26
                    a5 += (cm0 >> c) & 1u ? sp_pos(-z0) : sp_pos(z0);
                }
                // round 2: channels 32..63 -> classes 27..58
                {
                    int c = lid + 27;
                    unsigned bit = (c < 32) ? (cm0 >> c) : (cm1 >> (c - 32));
                    a5 += bit & 1u ? sp_pos(-z1) : sp_pos(z1);
                }
                // round 3: channels 64..84 -> classes 59..79 (lanes 0..20)
                if (lid < CH - 64) {
                    int c = lid + 59;
                    unsigned bit = (c < 64) ? (cm1 >> (c - 32)) : (cm2 >> (c - 64));
                    a5 += bit & 1u ? sp_pos(-z2) : sp_pos(z2);
                }
                // n_m: exactly one warp in the batch owns this target
                if (lid == 0) vals[6] = 1.f;
            }
        }
        vals[0] = a0; vals[1] = a1; vals[2] = a2;
        vals[3] = a3; vals[4] = a4; vals[5] = a5;

        // ---- 10-slot block reduction, one atomic per live slot ----
        #pragma unroll
        for (int j = 0; j < 10; j++) {
            float vv = vals[j];
            #pragma unroll
            for (int o = 16; o > 0; o >>= 1) vv += __shfl_down_sync(0xffffffffu, vv, o);
            if (lid == 0) red[j][wid] = vv;
        }
        __syncthreads();
        if (wid == 0) {
            #pragma unroll
            for (int j = 0; j < 10; j++) {
                float vv = (lid < NWARPS) ? red[j][lid] : 0.f;
                #pragma unroll
                for (int o = 4; o > 0; o >>= 1) vv += __shfl_down_sync(0xffffffffu, vv, o);
                if (lid == 0 && vv != 0.f) atomicAdd(&g_acc[j], vv);
            }
        }
    }

    // ======== completion: last block finalizes + resets state ========
    __threadfence();
    __syncthreads();
    if (tid == 0) s_last = atomicAdd(&g_done, 1u);
    __syncthreads();
    if (s_last == (unsigned)(NB_TOTAL - 1)) {
        if (tid == 0) {
            volatile float* g = g_acc;
            const float inv = 1.f / (float)CNT;
            float nm  = g[6];
            float nnm = (float)CNT - g[9];
            float lx = (g[0] * inv) / nm;
            float ly = (g[1] * inv) / nm;
            float lw = (g[2] * inv) / nm;
            float lh = (g[3] * inv) / nm;
            float lc = (g[4] * inv) / nm + 0.5f * ((g[7] - g[8]) * inv) / nnm;
            float lcls = g[5] / (nm * (float)C) / nm;
            float loss = 2.5f * (lx + ly) + 2.5f * (lw + lh) + lc + lcls;
            out[0] = loss; out[1] = lx; out[2] = ly; out[3] = lw;
            out[4] = lh;   out[5] = lc; out[6] = lcls;
        }
        __syncthreads();          // out written before reset
        if (tid < 10) g_acc[tid] = 0.f;
        __syncthreads();
        if (tid == 0) g_done = 0u;
    }
}

extern "C" void kernel_launch(void* const* d_in, const int* in_sizes, int n_in,
                              void* d_out, int out_size) {
    const float* inp = (const float*)d_in[0];
    const float* tgt = (const float*)d_in[1];
    if (n_in >= 2 && in_sizes[0] == B * T * 5) {   // defensive order check
        inp = (const float*)d_in[1];
        tgt = (const float*)d_in[0];
    }
    yolo_loss_all<<<NB_TOTAL, NTHREADS>>>(inp, tgt, (float*)d_out);
}